// round 13
// baseline (speedup 1.0000x reference)
#include <cuda_runtime.h>
#include <cuda_bf16.h>

#define N_G   4096
#define IMG_W 512
#define TILE  64
#define BLOCK 256
#define NB    592                    // 148 x 4 blocks — all co-resident
#define NSUB  1024                   // 64 tiles x 16 subtiles (16x16 px)
#define NJB   32
#define EXPSCALE (-0.72134752044f)   // -0.5 * log2(e)
#define QTHRN    (9.21034037f)       // 2 ln 100
#define LN2x2    (1.38629436112f)    // 2 ln 2
#define NEVMAX   264                 // 256 near + 8 warp-gap events

typedef unsigned long long u64;

__device__ float4 g_geo[N_G];        // px, py, radius (binning)
__device__ float4 g_bb [N_G];        // bbox: x0, x1, y0, y1
__device__ float4 g_cl [N_G];        // r, g, b, cd'
__device__ float4 g_ge [N_G];        // px, py, ca', cbc'
__device__ float  g_lp [N_G];        // log2(op)
__device__ int    g_prank[NJB][N_G];

__device__ float4 t_bb[64 * N_G], t_cl[64 * N_G], t_ge[64 * N_G];
__device__ float  t_lp[64 * N_G];
__device__ int    t_cnt[64];
__device__ int    c3a[64][8];
__device__ int    t_ready[64];

__device__ unsigned g_bar;
__device__ unsigned g_q;

__device__ __forceinline__ float ex2f(float x) {
    float y; asm("ex2.approx.f32 %0, %1;" : "=f"(y) : "f"(x)); return y;
}
__device__ __forceinline__ float rcpf(float x) {
    float y; asm("rcp.approx.f32 %0, %1;" : "=f"(y) : "f"(x)); return y;
}
__device__ __forceinline__ u64 pk2(float lo, float hi) {
    u64 r; asm("mov.b64 %0, {%1, %2};" : "=l"(r) : "f"(lo), "f"(hi)); return r;
}
__device__ __forceinline__ void upk2(float& lo, float& hi, u64 v) {
    asm("mov.b64 {%0, %1}, %2;" : "=f"(lo), "=f"(hi) : "l"(v));
}
__device__ __forceinline__ u64 fma2(u64 a, u64 b, u64 c) {
    u64 d; asm("fma.rn.f32x2 %0, %1, %2, %3;" : "=l"(d) : "l"(a), "l"(b), "l"(c)); return d;
}
__device__ __forceinline__ u64 mul2(u64 a, u64 b) {
    u64 d; asm("mul.rn.f32x2 %0, %1, %2;" : "=l"(d) : "l"(a), "l"(b)); return d;
}

struct SM {
    float4     n0[NEVMAX];           // px, py, ca', cbc'   (zeros for gap events)
    float2     n1[NEVMAX];           // lop2, -gP           (zeros for gap events)
    ulonglong2 p0[NEVMAX];           // cd2, (gP*colr)2
    ulonglong2 p1[NEVMAX];           // (gP*colg)2, (gP*colb)2
    ulonglong2 p2[NEVMAX];           // gapSr2, gapSg2
    ulonglong2 p3[NEVMAX];           // gapSb2, gP2
    int        wsum[8];
    int        item;
};

__device__ __forceinline__ int scan_bool(bool p, int* wsum, int& tot) {
    __syncthreads();
    const unsigned bits = __ballot_sync(0xffffffffu, p);
    const int lane = threadIdx.x & 31, wd = threadIdx.x >> 5;
    if (lane == 0) wsum[wd] = __popc(bits);
    __syncthreads();
    int off = 0, t = 0;
#pragma unroll
    for (int w = 0; w < 8; w++) { int c = wsum[w]; if (w < wd) off += c; t += c; }
    tot = t;
    return off + __popc(bits & ((1u << lane) - 1u));
}

__device__ __forceinline__ void grid_sync() {
    __syncthreads();
    if (threadIdx.x == 0) {
        __threadfence();
        unsigned v = atomicAdd(&g_bar, 1u);
        unsigned target = (v / NB + 1u) * NB;
        while (*(volatile unsigned*)&g_bar < target) { }
        __threadfence();
    }
    __syncthreads();
}

__global__ void __launch_bounds__(BLOCK, 4)
fused_kernel(const float* __restrict__ pos2d, const float* __restrict__ cov2d,
             const float* __restrict__ opacity, const float* __restrict__ color,
             float* __restrict__ out)
{
    __shared__ SM sm;
    const int tid = threadIdx.x;
    const int bid = blockIdx.x;
    const int lane = tid & 31, wd = tid >> 5;
    const unsigned FULL = 0xffffffffu;

    // ---------- Phase 1: counters reset + rank partials (blocks 0..511) --------
    if (bid == 0) {
        for (int k = tid; k < 64 * 8; k += BLOCK) ((int*)c3a)[k] = 0;
        for (int k = tid; k < 64; k += BLOCK) t_ready[k] = 0;
        if (tid == 0) g_q = 0;
    }
    if (bid < 512) {
        float* stage = (float*)sm.n0;
        const int ib = bid >> 5, jb = bid & 31;
        const int i = ib * BLOCK + tid;
        const int j0 = jb * 128;
        const float di = pos2d[i * 3 + 2];
        if (tid < 128) stage[tid] = pos2d[(j0 + tid) * 3 + 2];
        __syncthreads();
        int cnt = 0;
        const float4* sd4 = (const float4*)stage;
#pragma unroll 8
        for (int j = 0; j < 32; j++) {
            const float4 dj = sd4[j];
            const int g = j0 + j * 4;
            cnt += (dj.x < di) || (dj.x == di && (g + 0) < i);
            cnt += (dj.y < di) || (dj.y == di && (g + 1) < i);
            cnt += (dj.z < di) || (dj.z == di && (g + 2) < i);
            cnt += (dj.w < di) || (dj.w == di && (g + 3) < i);
        }
        g_prank[jb][i] = cnt;
    }
    grid_sync();

    // ---------- Phase 2: one warp per gaussian (512 blocks x 8 warps) ----------
    if (bid < 512) {
        const int i = bid * 8 + wd;
        int r = g_prank[lane][i];
#pragma unroll
        for (int d = 16; d > 0; d >>= 1) r += __shfl_down_sync(FULL, r, d);
        if (lane == 0) {
            const int rank = r;
            const float a = cov2d[i * 4 + 0];
            const float b = cov2d[i * 4 + 1];
            const float c = cov2d[i * 4 + 2];
            const float d = cov2d[i * 4 + 3];
            const float trace = a + d;
            const float det   = a * d - b * c;
            const float term2 = 0.5f * sqrtf(fmaxf(trace * trace - 4.0f * det, 0.0f));
            const float radius = 3.0f * sqrtf(fmaxf(0.5f * trace - term2, 0.5f * trace + term2));
            const float inv_det = 1.0f / det;

            const float px = pos2d[i * 3 + 0];
            const float py = pos2d[i * 3 + 1];
            const float lop2 = __log2f(opacity[i]);
            const float cr = fmaxf(color[i * 3 + 0] + 0.5f, 0.0f);
            const float cg = fmaxf(color[i * 3 + 1] + 0.5f, 0.0f);
            const float cb = fmaxf(color[i * 3 + 2] + 0.5f, 0.0f);

            const float cap  = EXPSCALE * d * inv_det;        // ca'
            const float cbcp = EXPSCALE * -(b + c) * inv_det; // cbc'
            const float cdp  = EXPSCALE * a * inv_det;        // cd'

            // opacity-adjusted near-bbox: q <= thr ellipse, thr = 2ln100 + 2ln(op)
            const float thr = QTHRN + LN2x2 * lop2;
            float4 bb;
            if (thr > 0.0f) {
                const float m = a * d - 0.25f * (b + c) * (b + c);
                const float s = thr * det / m;
                const float wx = sqrtf(s * a);
                const float wy = sqrtf(s * d);
                bb = make_float4(px - wx, px + wx, py - wy, py + wy);
            } else {
                bb = make_float4(1e30f, -1e30f, 1e30f, -1e30f);  // empty -> always far
            }

            g_geo[rank] = make_float4(px, py, radius, 0.0f);
            g_bb [rank] = bb;
            g_cl [rank] = make_float4(cr, cg, cb, cdp);
            g_ge [rank] = make_float4(px, py, cap, cbcp);
            g_lp [rank] = lop2;

            const int ch = rank >> 9;
            const int tx0 = max(0, (int)floorf((px - radius) * (1.f / 64.f)) - 1);
            const int tx1 = min(7, (int)floorf((px + radius) * (1.f / 64.f)) + 1);
            const int ty0 = max(0, (int)floorf((py - radius) * (1.f / 64.f)) - 1);
            const int ty1 = min(7, (int)floorf((py + radius) * (1.f / 64.f)) + 1);
            for (int tx = tx0; tx <= tx1; tx++) {
                const float left = (float)(tx * TILE);
                if (!((px + radius >= left) && (px - radius < left + (float)TILE))) continue;
                for (int ty = ty0; ty <= ty1; ty++) {
                    const float top = (float)(ty * TILE);
                    if ((py + radius >= top) && (py - radius < top + (float)TILE))
                        atomicAdd(&c3a[(tx << 3) | ty][ch], 1);
                }
            }
        }
    }
    grid_sync();

    // ---------- Phase 3: ordered compaction (blocks 0..511) --------------------
    if (bid < 512) {
        const int tile = bid >> 3, ch = bid & 7;
        const float left = (float)((tile >> 3) * TILE);
        const float top  = (float)((tile & 7) * TILE);
        int offset = 0, total = 0;
#pragma unroll
        for (int c = 0; c < 8; c++) {
            const int cc = c3a[tile][c];
            if (c < ch) offset += cc;
            total += cc;
        }
        if (ch == 0 && tid == 0) t_cnt[tile] = total;
        int outbase = offset;
#pragma unroll
        for (int r = 0; r < 2; r++) {
            const int g = ch * 512 + r * 256 + tid;
            const float4 geo = g_geo[g];
            const bool v = (geo.x + geo.z >= left) && (geo.x - geo.z < left + (float)TILE) &&
                           (geo.y + geo.z >= top)  && (geo.y - geo.z < top  + (float)TILE);
            int tot;
            const int pos = scan_bool(v, sm.wsum, tot);
            if (v) {
                const int o = tile * N_G + outbase + pos;
                t_bb[o] = g_bb[g];
                t_cl[o] = g_cl[g];
                t_ge[o] = g_ge[g];
                t_lp[o] = g_lp[g];
            }
            outbase += tot;
        }
        __syncthreads();
        if (tid == 0) {
            __threadfence();
            atomicAdd(&t_ready[tile], 1);
        }
    }

    // ---------- Phase 4: work-stealing render over 1024 subtiles (16x16) -------
    for (;;) {
        __syncthreads();
        if (tid == 0) sm.item = (int)atomicAdd(&g_q, 1u);
        __syncthreads();
        const int sub = sm.item;
        if (sub >= NSUB) break;

        const int ptile = sub >> 4, si = sub & 15;
        if (tid == 0) {
            while (*(volatile int*)&t_ready[ptile] < 8) __nanosleep(64);
            __threadfence();
        }
        __syncthreads();

        const int X0 = (ptile >> 3) * TILE + (si >> 2) * 16;
        const int Y0 = (ptile & 7) * TILE + (si & 3) * 16;
        const float rx0 = (float)X0, rx1 = (float)(X0 + 15);
        const float ry0 = (float)Y0, ry1 = (float)(Y0 + 15);

        const bool px_active = tid < 128;
        const int Xi  = X0 + (tid >> 3);
        const int Yi0 = Y0 + (tid & 7);
        const int Yi1 = Yi0 + 8;
        const float X = (float)Xi, Yf0 = (float)Yi0, Yf1 = (float)Yi1;

        const int cnt = t_cnt[ptile];
        const float4* __restrict__ BB = t_bb + ptile * N_G;
        const float4* __restrict__ CL = t_cl + ptile * N_G;
        const float4* __restrict__ GE = t_ge + ptile * N_G;
        const float*  __restrict__ LP = t_lp + ptile * N_G;

        u64 T2  = pk2(1.f, 1.f);
        u64 CR2 = pk2(0.f, 0.f), CG2 = CR2, CB2 = CR2;
        bool dead = !px_active;

        for (int c0 = 0; c0 < cnt; c0 += BLOCK) {
            const int L = cnt - c0;                 // remaining
            const bool validg = tid < L;
            float4 cl = make_float4(0,0,0,0);
            bool isnear = false, isfar = false;
            if (validg) {
                const float4 bb = BB[c0 + tid];
                cl = CL[c0 + tid];
                isnear = (bb.x <= rx1) && (bb.y >= rx0) && (bb.z <= ry1) && (bb.w >= ry0);
                isfar = !isnear;
            }

            // affine element: far -> (0.01*col, 0.99); near/invalid -> identity
            float aSr = 0.f, aSg = 0.f, aSb = 0.f, aP = 1.f;
            if (isfar) { aSr = 0.01f * cl.x; aSg = 0.01f * cl.y; aSb = 0.01f * cl.z; aP = 0.99f; }

            // warp-local inclusive affine scan
            float vSr = aSr, vSg = aSg, vSb = aSb, vP = aP;
#pragma unroll
            for (int d = 1; d < 32; d <<= 1) {
                const float uSr = __shfl_up_sync(FULL, vSr, d);
                const float uSg = __shfl_up_sync(FULL, vSg, d);
                const float uSb = __shfl_up_sync(FULL, vSb, d);
                const float uP  = __shfl_up_sync(FULL, vP,  d);
                if (lane >= d) {
                    vSr = fmaf(uP, vSr, uSr);
                    vSg = fmaf(uP, vSg, uSg);
                    vSb = fmaf(uP, vSb, uSb);
                    vP *= uP;
                }
            }
            // own exclusive prefix
            float eSr = __shfl_up_sync(FULL, vSr, 1);
            float eSg = __shfl_up_sync(FULL, vSg, 1);
            float eSb = __shfl_up_sync(FULL, vSb, 1);
            float eP  = __shfl_up_sync(FULL, vP,  1);
            if (lane == 0) { eSr = 0.f; eSg = 0.f; eSb = 0.f; eP = 1.f; }

            const unsigned nbits = __ballot_sync(FULL, isnear);
            const int nearcnt = __popc(nbits);
            const bool warpvalid = (wd * 32) < L;
            if (lane == 0) sm.wsum[wd] = nearcnt + (warpvalid ? 1 : 0);
            __syncthreads();                                   // bar 1

            int warpbase = 0, ntot = 0;
#pragma unroll
            for (int w = 0; w < 8; w++) {
                const int c = sm.wsum[w];
                if (w < wd) warpbase += c;
                ntot += c;
            }

            // within-warp gap for near lanes: previous near lane's exclusive prefix
            const unsigned mlt = nbits & ((1u << lane) - 1u);
            const int prevc = (mlt != 0u) ? (31 - __clz(mlt)) : 0;
            float qSr = __shfl_sync(FULL, eSr, prevc);
            float qSg = __shfl_sync(FULL, eSg, prevc);
            float qSb = __shfl_sync(FULL, eSb, prevc);
            float qP  = __shfl_sync(FULL, eP,  prevc);
            const bool hasprev = (mlt != 0u);
            const float pSr = hasprev ? qSr : 0.f;
            const float pSg = hasprev ? qSg : 0.f;
            const float pSb = hasprev ? qSb : 0.f;
            const float pP  = hasprev ? qP  : 1.f;
            const float irp = rcpf(pP);
            const float gSr = (eSr - pSr) * irp;
            const float gSg = (eSg - pSg) * irp;
            const float gSb = (eSb - pSb) * irp;
            const float gP  = eP * irp;

            // trailing gap: warp total vs last near's exclusive prefix
            const float TSr = __shfl_sync(FULL, vSr, 31);
            const float TSg = __shfl_sync(FULL, vSg, 31);
            const float TSb = __shfl_sync(FULL, vSb, 31);
            const float TPP = __shfl_sync(FULL, vP,  31);
            const int lastc = (nbits != 0u) ? (31 - __clz(nbits)) : 0;
            float wSr = __shfl_sync(FULL, eSr, lastc);
            float wSg = __shfl_sync(FULL, eSg, lastc);
            float wSb = __shfl_sync(FULL, eSb, lastc);
            float wP  = __shfl_sync(FULL, eP,  lastc);
            const bool hasnear = (nbits != 0u);
            const float lS0 = hasnear ? wSr : 0.f;
            const float lS1 = hasnear ? wSg : 0.f;
            const float lS2 = hasnear ? wSb : 0.f;
            const float lPP = hasnear ? wP  : 1.f;
            const float irl = rcpf(lPP);
            const float tgSr = (TSr - lS0) * irl;
            const float tgSg = (TSg - lS1) * irl;
            const float tgSb = (TSb - lS2) * irl;
            const float tgP  = TPP * irl;

            if (isnear) {
                const float4 ge = GE[c0 + tid];
                const float lop2v = LP[c0 + tid];
                const int pos = warpbase + __popc(mlt & nbits);
                const float gcr = gP * cl.x, gcg = gP * cl.y, gcb = gP * cl.z;
                sm.n0[pos] = ge;
                sm.n1[pos] = make_float2(lop2v, -gP);
                sm.p0[pos] = make_ulonglong2(pk2(cl.w, cl.w), pk2(gcr, gcr));
                sm.p1[pos] = make_ulonglong2(pk2(gcg, gcg), pk2(gcb, gcb));
                sm.p2[pos] = make_ulonglong2(pk2(gSr, gSr), pk2(gSg, gSg));
                sm.p3[pos] = make_ulonglong2(pk2(gSb, gSb), pk2(gP, gP));
            }
            if (lane == 31 && warpvalid) {
                const int pos = warpbase + nearcnt;
                sm.n0[pos] = make_float4(0.f, 0.f, 0.f, 0.f);
                sm.n1[pos] = make_float2(0.f, 0.f);
                sm.p0[pos] = make_ulonglong2(pk2(0.f, 0.f), pk2(0.f, 0.f));
                sm.p1[pos] = make_ulonglong2(pk2(0.f, 0.f), pk2(0.f, 0.f));
                sm.p2[pos] = make_ulonglong2(pk2(tgSr, tgSr), pk2(tgSg, tgSg));
                sm.p3[pos] = make_ulonglong2(pk2(tgSb, tgSb), pk2(tgP, tgP));
            }
            __syncthreads();                                   // bar 2

            // ---- pixel loop: f32x2-packed composite (threads 0..127) ----
            if (!dead) {
#pragma unroll 2
                for (int t = 0; t < ntot; t++) {
                    const float4     f0 = sm.n0[t];
                    const float2     h  = sm.n1[t];
                    const ulonglong2 q0 = sm.p0[t];
                    const ulonglong2 q1 = sm.p1[t];
                    const ulonglong2 q2 = sm.p2[t];
                    const ulonglong2 q3 = sm.p3[t];
                    const float dx  = X - f0.x;
                    const float tq  = fmaf(f0.z, dx * dx, h.x);
                    const float cdx = f0.w * dx;
                    const float dy0 = Yf0 - f0.y, dy1 = Yf1 - f0.y;
                    const u64 dy2   = pk2(dy0, dy1);
                    const u64 inner = fma2(q0.x, dy2, pk2(cdx, cdx));
                    const u64 e2    = fma2(dy2, inner, pk2(tq, tq));
                    float e0, e1; upk2(e0, e1, e2);
                    const float a0 = fminf(fmaxf(ex2f(e0), 0.01f), 0.99f);
                    const float a1 = fminf(fmaxf(ex2f(e1), 0.01f), 0.99f);
                    const u64 a2 = pk2(a0, a1);
                    const u64 sR = fma2(a2, q0.y, q2.x);
                    const u64 sG = fma2(a2, q1.x, q2.y);
                    const u64 sB = fma2(a2, q1.y, q3.x);
                    CR2 = fma2(T2, sR, CR2);
                    CG2 = fma2(T2, sG, CG2);
                    CB2 = fma2(T2, sB, CB2);
                    const u64 u2 = fma2(a2, pk2(h.y, h.y), q3.y);
                    T2 = mul2(T2, u2);
                }
                float T0f, T1f; upk2(T0f, T1f, T2);
                if (T0f < 1e-7f && T1f < 1e-7f) dead = true;
            }
            if (__syncthreads_count(dead ? 0 : 1) == 0) break;  // bar 3 (WAR guard)
        }

        if (px_active) {
            float C00, C10, C01, C11, C02, C12;
            upk2(C00, C10, CR2);
            upk2(C01, C11, CG2);
            upk2(C02, C12, CB2);
            const int ob0 = (Xi * IMG_W + Yi0) * 3;
            out[ob0 + 0] = C00; out[ob0 + 1] = C01; out[ob0 + 2] = C02;
            const int ob1 = (Xi * IMG_W + Yi1) * 3;
            out[ob1 + 0] = C10; out[ob1 + 1] = C11; out[ob1 + 2] = C12;
        }
    }
}

extern "C" void kernel_launch(void* const* d_in, const int* in_sizes, int n_in,
                              void* d_out, int out_size)
{
    const float* pos2d   = (const float*)d_in[0];
    const float* cov2d   = (const float*)d_in[1];
    const float* opacity = (const float*)d_in[2];
    const float* color   = (const float*)d_in[3];
    float* out = (float*)d_out;

    fused_kernel<<<NB, BLOCK>>>(pos2d, cov2d, opacity, color, out);
}

// round 14
// speedup vs baseline: 1.0518x; 1.0518x over previous
#include <cuda_runtime.h>
#include <cuda_bf16.h>

#define N_G   4096
#define IMG_W 512
#define TILE  64
#define BLOCK 256
#define NB    592                    // 148 x 4 blocks — all co-resident
#define NSUB  1024                   // 64 tiles x 16 subtiles (16x16 px)
#define NJB   32
#define EXPSCALE (-0.72134752044f)   // -0.5 * log2(e)
#define FTHR     (-6.64385619f)      // -2*log2(100)
#define CHUNK 128

typedef unsigned long long u64;

__device__ float4 g_geo[N_G];        // px, py, radius (binning)
__device__ float4 g_la [N_G];        // px, py, ca', cbc'
__device__ float4 g_lb [N_G];        // cd', log2(op), ha, r
__device__ float4 g_lc [N_G];        // g, b, hc, 0
__device__ int    g_prank[NJB][N_G];

__device__ float4 t_la[64 * N_G], t_lb[64 * N_G], t_lc[64 * N_G];
__device__ int    t_cnt[64];
__device__ int    c3a[64][8];
__device__ int    t_ready[64];

__device__ unsigned g_bar;
__device__ unsigned g_q;

__device__ __forceinline__ float ex2f(float x) {
    float y; asm("ex2.approx.f32 %0, %1;" : "=f"(y) : "f"(x)); return y;
}
__device__ __forceinline__ float rcpf(float x) {
    float y; asm("rcp.approx.f32 %0, %1;" : "=f"(y) : "f"(x)); return y;
}
__device__ __forceinline__ u64 pk2(float lo, float hi) {
    u64 r; asm("mov.b64 %0, {%1, %2};" : "=l"(r) : "f"(lo), "f"(hi)); return r;
}
__device__ __forceinline__ void upk2(float& lo, float& hi, u64 v) {
    asm("mov.b64 {%0, %1}, %2;" : "=f"(lo), "=f"(hi) : "l"(v));
}
__device__ __forceinline__ u64 fma2(u64 a, u64 b, u64 c) {
    u64 d; asm("fma.rn.f32x2 %0, %1, %2, %3;" : "=l"(d) : "l"(a), "l"(b), "l"(c)); return d;
}
__device__ __forceinline__ u64 mul2(u64 a, u64 b) {
    u64 d; asm("mul.rn.f32x2 %0, %1, %2;" : "=l"(d) : "l"(a), "l"(b)); return d;
}
__device__ __forceinline__ void pbar() {            // producer-group barrier (warps 0-3)
    asm volatile("bar.sync 1, 128;" ::: "memory");
}

struct Meta { int stop, first, last, ntot, itemid; float tS0, tS1, tS2, tP; };

struct SM {
    // double-buffered event stages
    float4     n0[2][CHUNK];
    float2     n1[2][CHUNK];
    ulonglong2 p0[2][CHUNK], p1[2][CHUNK], p2[2][CHUNK], p3[2][CHUNK];
    // producer scratch
    float sSr[CHUNK], sSg[CHUNK], sSb[CHUNK], sPp[CHUNK];
    float wsf[16];
    int   wsum[4];
    float carS0, carS1, carS2, carP;
    int   fetch;
    Meta  meta[2];
    // phase 1-3 scratch
    int   wsumP3[8];
};

__device__ __forceinline__ int scan_bool(bool p, int* wsum, int& tot) {
    __syncthreads();
    const unsigned bits = __ballot_sync(0xffffffffu, p);
    const int lane = threadIdx.x & 31, wd = threadIdx.x >> 5;
    if (lane == 0) wsum[wd] = __popc(bits);
    __syncthreads();
    int off = 0, t = 0;
#pragma unroll
    for (int w = 0; w < 8; w++) { int c = wsum[w]; if (w < wd) off += c; t += c; }
    tot = t;
    return off + __popc(bits & ((1u << lane) - 1u));
}

__device__ __forceinline__ void grid_sync() {
    __syncthreads();
    if (threadIdx.x == 0) {
        __threadfence();
        unsigned v = atomicAdd(&g_bar, 1u);
        unsigned target = (v / NB + 1u) * NB;
        while (*(volatile unsigned*)&g_bar < target) { }
        __threadfence();
    }
    __syncthreads();
}

__global__ void __launch_bounds__(BLOCK, 4)
fused_kernel(const float* __restrict__ pos2d, const float* __restrict__ cov2d,
             const float* __restrict__ opacity, const float* __restrict__ color,
             float* __restrict__ out)
{
    __shared__ SM sm;
    const int tid = threadIdx.x;
    const int bid = blockIdx.x;
    const int lane = tid & 31, wd = tid >> 5;
    const unsigned FULL = 0xffffffffu;

    // ---------- Phase 1: counters reset + rank partials (blocks 0..511) --------
    if (bid == 0) {
        for (int k = tid; k < 64 * 8; k += BLOCK) ((int*)c3a)[k] = 0;
        for (int k = tid; k < 64; k += BLOCK) t_ready[k] = 0;
        if (tid == 0) g_q = 0;
    }
    if (bid < 512) {
        float* stage = sm.sSr;
        const int ib = bid >> 5, jb = bid & 31;
        const int i = ib * BLOCK + tid;
        const int j0 = jb * 128;
        const float di = pos2d[i * 3 + 2];
        if (tid < 128) stage[tid] = pos2d[(j0 + tid) * 3 + 2];
        __syncthreads();
        int cnt = 0;
        const float4* sd4 = (const float4*)stage;
#pragma unroll 8
        for (int j = 0; j < 32; j++) {
            const float4 dj = sd4[j];
            const int g = j0 + j * 4;
            cnt += (dj.x < di) || (dj.x == di && (g + 0) < i);
            cnt += (dj.y < di) || (dj.y == di && (g + 1) < i);
            cnt += (dj.z < di) || (dj.z == di && (g + 2) < i);
            cnt += (dj.w < di) || (dj.w == di && (g + 3) < i);
        }
        g_prank[jb][i] = cnt;
    }
    grid_sync();

    // ---------- Phase 2: one warp per gaussian (512 blocks x 8 warps) ----------
    if (bid < 512) {
        const int i = bid * 8 + wd;
        int r = g_prank[lane][i];
#pragma unroll
        for (int d = 16; d > 0; d >>= 1) r += __shfl_down_sync(FULL, r, d);
        if (lane == 0) {
            const int rank = r;
            const float a = cov2d[i * 4 + 0];
            const float b = cov2d[i * 4 + 1];
            const float c = cov2d[i * 4 + 2];
            const float d = cov2d[i * 4 + 3];
            const float trace = a + d;
            const float det   = a * d - b * c;
            const float term2 = 0.5f * sqrtf(fmaxf(trace * trace - 4.0f * det, 0.0f));
            const float radius = 3.0f * sqrtf(fmaxf(0.5f * trace - term2, 0.5f * trace + term2));
            const float inv_det = 1.0f / det;

            const float px = pos2d[i * 3 + 0];
            const float py = pos2d[i * 3 + 1];
            const float lop2 = __log2f(opacity[i]);
            const float cr = fmaxf(color[i * 3 + 0] + 0.5f, 0.0f);
            const float cg = fmaxf(color[i * 3 + 1] + 0.5f, 0.0f);
            const float cb = fmaxf(color[i * 3 + 2] + 0.5f, 0.0f);

            const float cap  = EXPSCALE * d * inv_det;
            const float cbcp = EXPSCALE * -(b + c) * inv_det;
            const float cdp  = EXPSCALE * a * inv_det;
            const float hc = 0.5f * (b + c) / a;
            const float ha = 0.5f * (b + c) / d;

            g_geo[rank] = make_float4(px, py, radius, 0.0f);
            g_la [rank] = make_float4(px, py, cap, cbcp);
            g_lb [rank] = make_float4(cdp, lop2, ha, cr);
            g_lc [rank] = make_float4(cg, cb, hc, 0.0f);

            const int ch = rank >> 9;
            const int tx0 = max(0, (int)floorf((px - radius) * (1.f / 64.f)) - 1);
            const int tx1 = min(7, (int)floorf((px + radius) * (1.f / 64.f)) + 1);
            const int ty0 = max(0, (int)floorf((py - radius) * (1.f / 64.f)) - 1);
            const int ty1 = min(7, (int)floorf((py + radius) * (1.f / 64.f)) + 1);
            for (int tx = tx0; tx <= tx1; tx++) {
                const float left = (float)(tx * TILE);
                if (!((px + radius >= left) && (px - radius < left + (float)TILE))) continue;
                for (int ty = ty0; ty <= ty1; ty++) {
                    const float top = (float)(ty * TILE);
                    if ((py + radius >= top) && (py - radius < top + (float)TILE))
                        atomicAdd(&c3a[(tx << 3) | ty][ch], 1);
                }
            }
        }
    }
    grid_sync();

    // ---------- Phase 3: ordered compaction (blocks 0..511) --------------------
    if (bid < 512) {
        const int tile = bid >> 3, ch = bid & 7;
        const float left = (float)((tile >> 3) * TILE);
        const float top  = (float)((tile & 7) * TILE);
        int offset = 0, total = 0;
#pragma unroll
        for (int c = 0; c < 8; c++) {
            const int cc = c3a[tile][c];
            if (c < ch) offset += cc;
            total += cc;
        }
        if (ch == 0 && tid == 0) t_cnt[tile] = total;
        int outbase = offset;
#pragma unroll
        for (int r = 0; r < 2; r++) {
            const int g = ch * 512 + r * 256 + tid;
            const float4 geo = g_geo[g];
            const bool v = (geo.x + geo.z >= left) && (geo.x - geo.z < left + (float)TILE) &&
                           (geo.y + geo.z >= top)  && (geo.y - geo.z < top  + (float)TILE);
            int tot;
            const int pos = scan_bool(v, sm.wsumP3, tot);
            if (v) {
                const int o = tile * N_G + outbase + pos;
                t_la[o] = g_la[g];
                t_lb[o] = g_lb[g];
                t_lc[o] = g_lc[g];
            }
            outbase += tot;
        }
        __syncthreads();
        if (tid == 0) {
            __threadfence();
            atomicAdd(&t_ready[tile], 1);
        }
    }
    // no grid sync: phase 4 uses t_ready

    // ---------- Phase 4: warp-specialized producer/consumer pipeline -----------
    {
        const bool isprod = tid < 128;
        const int  ct = tid - 128;                 // consumer index 0..127

        // producer state (uniform across producer threads)
        int  cur_item = -1, pc0 = 0, pcnt = 0, pbase = 0;
        float prx0 = 0, prx1 = 0, pry0 = 0, pry1 = 0;
        bool pdone = false;

        // consumer state
        u64 T2 = pk2(1.f, 1.f), CR2 = pk2(0.f, 0.f), CG2 = CR2, CB2 = CR2;
        float cX = 0, cY0 = 0, cY1 = 0;
        int cXi = 0, cYi0 = 0, cYi1 = 0;

        int sp = 0, sc = -1;
        for (;;) {
            if (isprod && !pdone) {
                const int slot = sp & 1;
                int firstflag = 0;
                bool skip = false;
                if (cur_item < 0) {
                    if (tid == 0) sm.fetch = (int)atomicAdd(&g_q, 1u);
                    pbar();
                    const int it = sm.fetch;
                    if (it >= NSUB) {
                        if (tid == 0) sm.meta[slot].stop = 1;
                        pdone = true;
                        skip = true;
                    } else {
                        cur_item = it;
                        const int ptile = it >> 4, si = it & 15;
                        const int X0 = (ptile >> 3) * TILE + (si >> 2) * 16;
                        const int Y0 = (ptile & 7) * TILE + (si & 3) * 16;
                        prx0 = (float)X0; prx1 = (float)(X0 + 15);
                        pry0 = (float)Y0; pry1 = (float)(Y0 + 15);
                        pbase = ptile * N_G;
                        if (tid == 0) {
                            while (*(volatile int*)&t_ready[ptile] < 8) __nanosleep(64);
                            __threadfence();
                            sm.carS0 = 0.f; sm.carS1 = 0.f; sm.carS2 = 0.f; sm.carP = 1.f;
                        }
                        pbar();
                        pcnt = t_cnt[(it >> 4)];
                        pc0 = 0;
                        firstflag = 1;
                    }
                }
                if (!skip) {
                    const int L = pcnt - pc0;
                    const bool validg = tid < L;
                    float4 la = make_float4(0,0,0,0), lb = make_float4(0,0,0,0), lc = make_float4(0,0,0,0);
                    bool isnear = false;
                    if (validg) {
                        la = t_la[pbase + pc0 + tid];
                        lb = t_lb[pbase + pc0 + tid];
                        lc = t_lc[pbase + pc0 + tid];
                        const float dxlo = prx0 - la.x, dxhi = prx1 - la.x;
                        const float dylo = pry0 - la.y, dyhi = pry1 - la.y;
                        const bool inside = (dxlo <= 0.f) && (dxhi >= 0.f) &&
                                            (dylo <= 0.f) && (dyhi >= 0.f);
                        float qsm = 0.0f;
                        if (!inside) {
                            const float hc = lc.z, ha = lb.z;
                            float dys = fminf(fmaxf(hc * dxlo, dylo), dyhi);
                            qsm = fmaf(fmaf(la.w, dys, la.z * dxlo), dxlo, lb.x * dys * dys);
                            dys = fminf(fmaxf(hc * dxhi, dylo), dyhi);
                            qsm = fmaxf(qsm, fmaf(fmaf(la.w, dys, la.z * dxhi), dxhi, lb.x * dys * dys));
                            float dxs = fminf(fmaxf(ha * dylo, dxlo), dxhi);
                            qsm = fmaxf(qsm, fmaf(fmaf(la.w, dxs, lb.x * dylo), dylo, la.z * dxs * dxs));
                            dxs = fminf(fmaxf(ha * dyhi, dxlo), dxhi);
                            qsm = fmaxf(qsm, fmaf(fmaf(la.w, dxs, lb.x * dyhi), dyhi, la.z * dxs * dxs));
                        }
                        isnear = !(qsm < (FTHR - lb.y));
                    }
                    const bool isfar = validg && !isnear;

                    float aSr = 0.f, aSg = 0.f, aSb = 0.f, aP = 1.f;
                    if (isfar) { aSr = 0.01f * lb.w; aSg = 0.01f * lc.x; aSb = 0.01f * lc.y; aP = 0.99f; }

                    float vSr = aSr, vSg = aSg, vSb = aSb, vP = aP;
#pragma unroll
                    for (int d = 1; d < 32; d <<= 1) {
                        const float uSr = __shfl_up_sync(FULL, vSr, d);
                        const float uSg = __shfl_up_sync(FULL, vSg, d);
                        const float uSb = __shfl_up_sync(FULL, vSb, d);
                        const float uP  = __shfl_up_sync(FULL, vP,  d);
                        if (lane >= d) {
                            vSr = fmaf(uP, vSr, uSr);
                            vSg = fmaf(uP, vSg, uSg);
                            vSb = fmaf(uP, vSb, uSb);
                            vP *= uP;
                        }
                    }
                    float eSr = __shfl_up_sync(FULL, vSr, 1);
                    float eSg = __shfl_up_sync(FULL, vSg, 1);
                    float eSb = __shfl_up_sync(FULL, vSb, 1);
                    float eP  = __shfl_up_sync(FULL, vP,  1);
                    if (lane == 0) { eSr = 0.f; eSg = 0.f; eSb = 0.f; eP = 1.f; }

                    const unsigned nbits = __ballot_sync(FULL, isnear);
                    const int pwd = tid >> 5;                  // 0..3
                    if (lane == 31) {
                        sm.wsf[pwd*4+0] = vSr; sm.wsf[pwd*4+1] = vSg;
                        sm.wsf[pwd*4+2] = vSb; sm.wsf[pwd*4+3] = vP;
                        sm.wsum[pwd] = __popc(nbits);
                    }
                    pbar();
                    // carry from previous chunk (stable since last producer barrier)
                    const float cS0 = sm.carS0, cS1 = sm.carS1, cS2 = sm.carS2, cPP = sm.carP;

                    float oS0 = 0.f, oS1 = 0.f, oS2 = 0.f, oP = 1.f;
                    float t0 = 0.f, t1 = 0.f, t2 = 0.f, tp = 1.f;
                    int ioff = 0, ntot = 0;
#pragma unroll
                    for (int w = 0; w < 4; w++) {
                        const float w0 = sm.wsf[w*4+0], w1 = sm.wsf[w*4+1];
                        const float w2 = sm.wsf[w*4+2], wp = sm.wsf[w*4+3];
                        const int wc = sm.wsum[w];
                        if (w < pwd) {
                            oS0 = fmaf(oP, w0, oS0); oS1 = fmaf(oP, w1, oS1);
                            oS2 = fmaf(oP, w2, oS2); oP *= wp;
                            ioff += wc;
                        }
                        t0 = fmaf(tp, w0, t0); t1 = fmaf(tp, w1, t1);
                        t2 = fmaf(tp, w2, t2); tp *= wp;
                        ntot += wc;
                    }
                    const float ES0 = fmaf(oP, eSr, oS0);
                    const float ES1 = fmaf(oP, eSg, oS1);
                    const float ES2 = fmaf(oP, eSb, oS2);
                    const float EP  = oP * eP;

                    const unsigned mlt = nbits & ((1u << lane) - 1u);
                    const int nidx = ioff + __popc(mlt);
                    if (isnear) {
                        sm.sSr[nidx] = ES0; sm.sSg[nidx] = ES1;
                        sm.sSb[nidx] = ES2; sm.sPp[nidx] = EP;
                        sm.n0[slot][nidx] = la;
                    }
                    pbar();
                    if (isnear) {
                        float gSr, gSg, gSb, gP;
                        if (nidx > 0) {
                            const float pS0 = sm.sSr[nidx-1], pS1 = sm.sSg[nidx-1];
                            const float pS2 = sm.sSb[nidx-1], pP = sm.sPp[nidx-1];
                            const float ir = rcpf(pP);
                            gSr = (ES0 - pS0) * ir;
                            gSg = (ES1 - pS1) * ir;
                            gSb = (ES2 - pS2) * ir;
                            gP  = EP * ir;
                        } else {
                            gSr = fmaf(cPP, ES0, cS0);
                            gSg = fmaf(cPP, ES1, cS1);
                            gSb = fmaf(cPP, ES2, cS2);
                            gP  = cPP * EP;
                        }
                        const float gcr = gP * lb.w, gcg = gP * lc.x, gcb = gP * lc.y;
                        sm.n1[slot][nidx] = make_float2(lb.y, -gP);
                        sm.p0[slot][nidx] = make_ulonglong2(pk2(lb.x, lb.x), pk2(gcr, gcr));
                        sm.p1[slot][nidx] = make_ulonglong2(pk2(gcg, gcg), pk2(gcb, gcb));
                        sm.p2[slot][nidx] = make_ulonglong2(pk2(gSr, gSr), pk2(gSg, gSg));
                        sm.p3[slot][nidx] = make_ulonglong2(pk2(gSb, gSb), pk2(gP, gP));
                    }
                    const bool lastchunk = (pc0 + CHUNK >= pcnt);
                    if (tid == 0) {
                        float nS0, nS1, nS2, nP;
                        if (ntot > 0) {
                            const float lS0 = sm.sSr[ntot-1], lS1 = sm.sSg[ntot-1];
                            const float lS2 = sm.sSb[ntot-1], lP = sm.sPp[ntot-1];
                            const float ir = rcpf(lP);
                            nS0 = (t0 - lS0) * ir; nS1 = (t1 - lS1) * ir;
                            nS2 = (t2 - lS2) * ir; nP = tp * ir;
                        } else {
                            nS0 = fmaf(cPP, t0, cS0); nS1 = fmaf(cPP, t1, cS1);
                            nS2 = fmaf(cPP, t2, cS2); nP = cPP * tp;
                        }
                        sm.carS0 = nS0; sm.carS1 = nS1; sm.carS2 = nS2; sm.carP = nP;
                        Meta& M = sm.meta[slot];
                        M.stop = 0; M.first = firstflag; M.last = lastchunk ? 1 : 0;
                        M.ntot = ntot; M.itemid = cur_item;
                        M.tS0 = nS0; M.tS1 = nS1; M.tS2 = nS2; M.tP = nP;
                    }
                    if (lastchunk) cur_item = -1; else pc0 += CHUNK;
                }
                sp++;
            }
            __syncthreads();
            sc++;
            const Meta m = sm.meta[sc & 1];
            if (m.stop) break;
            if (!isprod) {
                if (m.first) {
                    const int ptile = m.itemid >> 4, si = m.itemid & 15;
                    const int X0 = (ptile >> 3) * TILE + (si >> 2) * 16;
                    const int Y0 = (ptile & 7) * TILE + (si & 3) * 16;
                    cXi = X0 + (ct >> 3); cYi0 = Y0 + (ct & 7); cYi1 = cYi0 + 8;
                    cX = (float)cXi; cY0 = (float)cYi0; cY1 = (float)cYi1;
                    T2 = pk2(1.f, 1.f); CR2 = pk2(0.f, 0.f); CG2 = CR2; CB2 = CR2;
                }
                const int slot = sc & 1;
                const int nt = m.ntot;
#pragma unroll 2
                for (int t = 0; t < nt; t++) {
                    const float4     f0 = sm.n0[slot][t];
                    const float2     h  = sm.n1[slot][t];
                    const ulonglong2 q0 = sm.p0[slot][t];
                    const ulonglong2 q1 = sm.p1[slot][t];
                    const ulonglong2 q2 = sm.p2[slot][t];
                    const ulonglong2 q3 = sm.p3[slot][t];
                    const float dx  = cX - f0.x;
                    const float tq  = fmaf(f0.z, dx * dx, h.x);
                    const float cdx = f0.w * dx;
                    const float dy0 = cY0 - f0.y, dy1 = cY1 - f0.y;
                    const u64 dy2   = pk2(dy0, dy1);
                    const u64 inner = fma2(q0.x, dy2, pk2(cdx, cdx));
                    const u64 e2    = fma2(dy2, inner, pk2(tq, tq));
                    float e0, e1; upk2(e0, e1, e2);
                    const float a0 = fminf(fmaxf(ex2f(e0), 0.01f), 0.99f);
                    const float a1 = fminf(fmaxf(ex2f(e1), 0.01f), 0.99f);
                    const u64 a2 = pk2(a0, a1);
                    const u64 sR = fma2(a2, q0.y, q2.x);
                    const u64 sG = fma2(a2, q1.x, q2.y);
                    const u64 sB = fma2(a2, q1.y, q3.x);
                    CR2 = fma2(T2, sR, CR2);
                    CG2 = fma2(T2, sG, CG2);
                    CB2 = fma2(T2, sB, CB2);
                    const u64 u2 = fma2(a2, pk2(h.y, h.y), q3.y);
                    T2 = mul2(T2, u2);
                }
                if (m.last) {
                    CR2 = fma2(T2, pk2(m.tS0, m.tS0), CR2);
                    CG2 = fma2(T2, pk2(m.tS1, m.tS1), CG2);
                    CB2 = fma2(T2, pk2(m.tS2, m.tS2), CB2);
                    float C00, C10, C01, C11, C02, C12;
                    upk2(C00, C10, CR2);
                    upk2(C01, C11, CG2);
                    upk2(C02, C12, CB2);
                    const int ob0 = (cXi * IMG_W + cYi0) * 3;
                    out[ob0 + 0] = C00; out[ob0 + 1] = C01; out[ob0 + 2] = C02;
                    const int ob1 = (cXi * IMG_W + cYi1) * 3;
                    out[ob1 + 0] = C10; out[ob1 + 1] = C11; out[ob1 + 2] = C12;
                }
            }
        }
    }
}

extern "C" void kernel_launch(void* const* d_in, const int* in_sizes, int n_in,
                              void* d_out, int out_size)
{
    const float* pos2d   = (const float*)d_in[0];
    const float* cov2d   = (const float*)d_in[1];
    const float* opacity = (const float*)d_in[2];
    const float* color   = (const float*)d_in[3];
    float* out = (float*)d_out;

    fused_kernel<<<NB, BLOCK>>>(pos2d, cov2d, opacity, color, out);
}

// round 15
// speedup vs baseline: 1.1233x; 1.0680x over previous
#include <cuda_runtime.h>
#include <cuda_bf16.h>

#define N_G   4096
#define IMG_W 512
#define TILE  64
#define BLOCK 256
#define NB    592                    // 148 x 4 blocks — all co-resident
#define NSUB  1024                   // 64 tiles x 16 subtiles (16x16 px)
#define NBUCK 1024
#define BCAP  64
#define EXPSCALE (-0.72134752044f)   // -0.5 * log2(e)
#define FTHR     (-6.64385619f)      // -2*log2(100)

typedef unsigned long long u64;

__device__ float4 g_geo[N_G];        // px, py, radius (binning)
__device__ float4 g_la [N_G];        // px, py, ca', cbc'
__device__ float4 g_lb [N_G];        // cd', log2(op), ha, r
__device__ float4 g_lc [N_G];        // g, b, hc, 0
__device__ int    g_hist[NBUCK];     // bucket counts (zeroed at end of each launch)
__device__ u64    g_bkey[NBUCK * BCAP];

__device__ float4 t_la[64 * N_G], t_lb[64 * N_G], t_lc[64 * N_G];
__device__ int    t_cnt[64];
__device__ int    c3a[64][8];
__device__ int    t_ready[64];

__device__ unsigned g_bar;
__device__ unsigned g_q;

__device__ __forceinline__ float ex2f(float x) {
    float y; asm("ex2.approx.f32 %0, %1;" : "=f"(y) : "f"(x)); return y;
}
__device__ __forceinline__ float rcpf(float x) {
    float y; asm("rcp.approx.f32 %0, %1;" : "=f"(y) : "f"(x)); return y;
}
__device__ __forceinline__ u64 pk2(float lo, float hi) {
    u64 r; asm("mov.b64 %0, {%1, %2};" : "=l"(r) : "f"(lo), "f"(hi)); return r;
}
__device__ __forceinline__ void upk2(float& lo, float& hi, u64 v) {
    asm("mov.b64 {%0, %1}, %2;" : "=f"(lo), "=f"(hi) : "l"(v));
}
__device__ __forceinline__ u64 fma2(u64 a, u64 b, u64 c) {
    u64 d; asm("fma.rn.f32x2 %0, %1, %2, %3;" : "=l"(d) : "l"(a), "l"(b), "l"(c)); return d;
}
__device__ __forceinline__ u64 mul2(u64 a, u64 b) {
    u64 d; asm("mul.rn.f32x2 %0, %1, %2;" : "=l"(d) : "l"(a), "l"(b)); return d;
}
__device__ __forceinline__ int dbucket(float d) {
    int b = (int)((d - 0.1f) * 102.4f);
    return max(0, min(NBUCK - 1, b));
}

struct SM {
    float4     n0[BLOCK];            // px, py, ca', cbc'   (phase D: aliased as s_h)
    float2     n1[BLOCK];            // lop2, -gP
    ulonglong2 p0[BLOCK];            // cd2, (gP*colr)2     (phase D: aliased as s_bs)
    ulonglong2 p1[BLOCK];            // (gP*colg)2, (gP*colb)2
    ulonglong2 p2[BLOCK];            // gapSr2, gapSg2
    ulonglong2 p3[BLOCK];            // gapSb2, gP2
    float      sSr[BLOCK], sSg[BLOCK], sSb[BLOCK], sP[BLOCK];
    int        wsum[8];
    float      wsf[32];
    float      wsf2[36];
    int        wsum2[8];
    int        sncnt;
    float      tailSr, tailSg, tailSb, tailP;
    int        item;
};

__device__ __forceinline__ int scan_bool(bool p, int* wsum, int& tot) {
    __syncthreads();
    const unsigned bits = __ballot_sync(0xffffffffu, p);
    const int lane = threadIdx.x & 31, wd = threadIdx.x >> 5;
    if (lane == 0) wsum[wd] = __popc(bits);
    __syncthreads();
    int off = 0, t = 0;
#pragma unroll
    for (int w = 0; w < 8; w++) { int c = wsum[w]; if (w < wd) off += c; t += c; }
    tot = t;
    return off + __popc(bits & ((1u << lane) - 1u));
}

__device__ __forceinline__ void grid_sync() {
    __syncthreads();
    if (threadIdx.x == 0) {
        __threadfence();
        unsigned v = atomicAdd(&g_bar, 1u);
        unsigned target = (v / NB + 1u) * NB;
        while (*(volatile unsigned*)&g_bar < target) { }
        __threadfence();
    }
    __syncthreads();
}

__global__ void __launch_bounds__(BLOCK, 4)
fused_kernel(const float* __restrict__ pos2d, const float* __restrict__ cov2d,
             const float* __restrict__ opacity, const float* __restrict__ color,
             float* __restrict__ out)
{
    __shared__ SM sm;
    const int tid = threadIdx.x;
    const int bid = blockIdx.x;
    const int lane = tid & 31, wd = tid >> 5;
    const unsigned FULL = 0xffffffffu;

    // ---------- Phase B: bucket scatter (blocks 0..15) + counter reset ---------
    if (bid < 16) {
        const int i = bid * BLOCK + tid;
        const float d = pos2d[i * 3 + 2];
        const int b = dbucket(d);
        const int slot = atomicAdd(&g_hist[b], 1);
        if (slot < BCAP)
            g_bkey[(b << 6) + slot] = ((u64)__float_as_uint(d) << 32) | (unsigned)i;
    } else if (bid == 16) {
        for (int k = tid; k < 64 * 8; k += BLOCK) ((int*)c3a)[k] = 0;
        for (int k = tid; k < 64; k += BLOCK) t_ready[k] = 0;
        if (tid == 0) g_q = 0;
    }
    grid_sync();

    // ---------- Phase D: prefix + exact rank + params + bins (blocks 0..255) ---
    if (bid < 256) {
        int* s_h  = (int*)sm.n0;    // 1024 ints
        int* s_bs = (int*)sm.p0;    // 1024 ints
        for (int k = tid; k < NBUCK; k += BLOCK) s_h[k] = min(g_hist[k], BCAP);
        __syncthreads();
        const int t4 = tid * 4;
        const int h0 = s_h[t4], h1 = s_h[t4+1], h2 = s_h[t4+2], h3 = s_h[t4+3];
        const int sum4 = h0 + h1 + h2 + h3;
        int inc = sum4;
#pragma unroll
        for (int d = 1; d < 32; d <<= 1) {
            const int u = __shfl_up_sync(FULL, inc, d);
            if (lane >= d) inc += u;
        }
        if (lane == 31) sm.wsum[wd] = inc;
        __syncthreads();
        int woff = 0;
#pragma unroll
        for (int w = 0; w < 8; w++) if (w < wd) woff += sm.wsum[w];
        const int excl = woff + inc - sum4;
        s_bs[t4]     = excl;
        s_bs[t4 + 1] = excl + h0;
        s_bs[t4 + 2] = excl + h0 + h1;
        s_bs[t4 + 3] = excl + h0 + h1 + h2;
        __syncthreads();

        if (tid < 16) {
            const int i = bid * 16 + tid;
            const float dep = pos2d[i * 3 + 2];
            const u64 ki = ((u64)__float_as_uint(dep) << 32) | (unsigned)i;
            const int bk = dbucket(dep);
            const int cnt = s_h[bk];
            int rank = s_bs[bk];
#pragma unroll 4
            for (int j = 0; j < cnt; j++)
                rank += (g_bkey[(bk << 6) + j] < ki) ? 1 : 0;

            const float a = cov2d[i * 4 + 0];
            const float b = cov2d[i * 4 + 1];
            const float c = cov2d[i * 4 + 2];
            const float d = cov2d[i * 4 + 3];
            const float trace = a + d;
            const float det   = a * d - b * c;
            const float term2 = 0.5f * sqrtf(fmaxf(trace * trace - 4.0f * det, 0.0f));
            const float radius = 3.0f * sqrtf(fmaxf(0.5f * trace - term2, 0.5f * trace + term2));
            const float inv_det = 1.0f / det;

            const float px = pos2d[i * 3 + 0];
            const float py = pos2d[i * 3 + 1];
            const float lop2 = __log2f(opacity[i]);
            const float cr = fmaxf(color[i * 3 + 0] + 0.5f, 0.0f);
            const float cg = fmaxf(color[i * 3 + 1] + 0.5f, 0.0f);
            const float cb = fmaxf(color[i * 3 + 2] + 0.5f, 0.0f);

            const float cap  = EXPSCALE * d * inv_det;
            const float cbcp = EXPSCALE * -(b + c) * inv_det;
            const float cdp  = EXPSCALE * a * inv_det;
            const float hc = 0.5f * (b + c) / a;
            const float ha = 0.5f * (b + c) / d;

            g_geo[rank] = make_float4(px, py, radius, 0.0f);
            g_la [rank] = make_float4(px, py, cap, cbcp);
            g_lb [rank] = make_float4(cdp, lop2, ha, cr);
            g_lc [rank] = make_float4(cg, cb, hc, 0.0f);

            const int ch = rank >> 9;
            const int tx0 = max(0, (int)floorf((px - radius) * (1.f / 64.f)) - 1);
            const int tx1 = min(7, (int)floorf((px + radius) * (1.f / 64.f)) + 1);
            const int ty0 = max(0, (int)floorf((py - radius) * (1.f / 64.f)) - 1);
            const int ty1 = min(7, (int)floorf((py + radius) * (1.f / 64.f)) + 1);
            for (int tx = tx0; tx <= tx1; tx++) {
                const float left = (float)(tx * TILE);
                if (!((px + radius >= left) && (px - radius < left + (float)TILE))) continue;
                for (int ty = ty0; ty <= ty1; ty++) {
                    const float top = (float)(ty * TILE);
                    if ((py + radius >= top) && (py - radius < top + (float)TILE))
                        atomicAdd(&c3a[(tx << 3) | ty][ch], 1);
                }
            }
        }
    }
    grid_sync();

    // ---------- Phase 3: ordered compaction (blocks 0..511); 512 zeroes hist ---
    if (bid < 512) {
        const int tile = bid >> 3, ch = bid & 7;
        const float left = (float)((tile >> 3) * TILE);
        const float top  = (float)((tile & 7) * TILE);
        int offset = 0, total = 0;
#pragma unroll
        for (int c = 0; c < 8; c++) {
            const int cc = c3a[tile][c];
            if (c < ch) offset += cc;
            total += cc;
        }
        if (ch == 0 && tid == 0) t_cnt[tile] = total;
        int outbase = offset;
#pragma unroll
        for (int r = 0; r < 2; r++) {
            const int g = ch * 512 + r * 256 + tid;
            const float4 geo = g_geo[g];
            const bool v = (geo.x + geo.z >= left) && (geo.x - geo.z < left + (float)TILE) &&
                           (geo.y + geo.z >= top)  && (geo.y - geo.z < top  + (float)TILE);
            int tot;
            const int pos = scan_bool(v, sm.wsum, tot);
            if (v) {
                const int o = tile * N_G + outbase + pos;
                t_la[o] = g_la[g];
                t_lb[o] = g_lb[g];
                t_lc[o] = g_lc[g];
            }
            outbase += tot;
        }
        __syncthreads();
        if (tid == 0) {
            __threadfence();
            atomicAdd(&t_ready[tile], 1);
        }
    } else if (bid == 512) {
        // hist consumed only by phases B/D; re-zero here for the next launch
        for (int k = tid; k < NBUCK; k += BLOCK) g_hist[k] = 0;
    }

    // ---------- Phase 4: work-stealing render over 1024 subtiles (16x16) -------
    for (;;) {
        __syncthreads();
        if (tid == 0) sm.item = (int)atomicAdd(&g_q, 1u);
        __syncthreads();
        const int sub = sm.item;
        if (sub >= NSUB) break;

        const int ptile = sub >> 4, si = sub & 15;
        if (tid == 0) {
            while (*(volatile int*)&t_ready[ptile] < 8) __nanosleep(64);
            __threadfence();
        }
        __syncthreads();

        const int X0 = (ptile >> 3) * TILE + (si >> 2) * 16;
        const int Y0 = (ptile & 7) * TILE + (si & 3) * 16;
        const float rx0 = (float)X0, rx1 = (float)(X0 + 15);
        const float ry0 = (float)Y0, ry1 = (float)(Y0 + 15);

        const bool px_active = tid < 128;
        const int Xi  = X0 + (tid >> 3);
        const int Yi0 = Y0 + (tid & 7);
        const int Yi1 = Yi0 + 8;
        const float X = (float)Xi, Yf0 = (float)Yi0, Yf1 = (float)Yi1;

        const int cnt = t_cnt[ptile];
        const float4* __restrict__ LA = t_la + ptile * N_G;
        const float4* __restrict__ LB = t_lb + ptile * N_G;
        const float4* __restrict__ LC = t_lc + ptile * N_G;

        u64 T2  = pk2(1.f, 1.f);
        u64 CR2 = pk2(0.f, 0.f), CG2 = CR2, CB2 = CR2;
        bool dead = !px_active;

        for (int c0 = 0; c0 < cnt; c0 += BLOCK) {
            const int L = cnt - c0;
            const bool validg = tid < L;
            float4 la = make_float4(0,0,0,0), lb = make_float4(0,0,0,0), lc = make_float4(0,0,0,0);
            bool isfar = false;
            if (validg) {
                la = LA[c0 + tid]; lb = LB[c0 + tid]; lc = LC[c0 + tid];
                const float dxlo = rx0 - la.x, dxhi = rx1 - la.x;
                const float dylo = ry0 - la.y, dyhi = ry1 - la.y;
                const bool inside = (dxlo <= 0.f) && (dxhi >= 0.f) &&
                                    (dylo <= 0.f) && (dyhi >= 0.f);
                float qsm = 0.0f;
                if (!inside) {
                    const float hc = lc.z, ha = lb.z;
                    float dys = fminf(fmaxf(hc * dxlo, dylo), dyhi);
                    qsm = fmaf(fmaf(la.w, dys, la.z * dxlo), dxlo, lb.x * dys * dys);
                    dys = fminf(fmaxf(hc * dxhi, dylo), dyhi);
                    qsm = fmaxf(qsm, fmaf(fmaf(la.w, dys, la.z * dxhi), dxhi, lb.x * dys * dys));
                    float dxs = fminf(fmaxf(ha * dylo, dxlo), dxhi);
                    qsm = fmaxf(qsm, fmaf(fmaf(la.w, dxs, lb.x * dylo), dylo, la.z * dxs * dxs));
                    dxs = fminf(fmaxf(ha * dyhi, dxlo), dxhi);
                    qsm = fmaxf(qsm, fmaf(fmaf(la.w, dxs, lb.x * dyhi), dyhi, la.z * dxs * dxs));
                }
                isfar = qsm < (FTHR - lb.y);
            }
            const bool isnear = validg && !isfar;

            float aSr = 0.f, aSg = 0.f, aSb = 0.f, aP = 1.f;
            if (isfar) { aSr = 0.01f * lb.w; aSg = 0.01f * lc.x; aSb = 0.01f * lc.y; aP = 0.99f; }

            float vSr = aSr, vSg = aSg, vSb = aSb, vP = aP;
#pragma unroll
            for (int d = 1; d < 32; d <<= 1) {
                const float uSr = __shfl_up_sync(FULL, vSr, d);
                const float uSg = __shfl_up_sync(FULL, vSg, d);
                const float uSb = __shfl_up_sync(FULL, vSb, d);
                const float uP  = __shfl_up_sync(FULL, vP,  d);
                if (lane >= d) {
                    vSr = fmaf(uP, vSr, uSr);
                    vSg = fmaf(uP, vSg, uSg);
                    vSb = fmaf(uP, vSb, uSb);
                    vP *= uP;
                }
            }
            const unsigned nbits = __ballot_sync(FULL, isnear);
            if (lane == 31) {
                sm.wsf[wd*4+0] = vSr; sm.wsf[wd*4+1] = vSg;
                sm.wsf[wd*4+2] = vSb; sm.wsf[wd*4+3] = vP;
                sm.wsum[wd] = __popc(nbits);
            }
            __syncthreads();

            if (wd == 0) {
                float wSr = 0.f, wSg = 0.f, wSb = 0.f, wP = 1.f;
                int wc = 0;
                if (lane < 8) {
                    wSr = sm.wsf[lane*4+0]; wSg = sm.wsf[lane*4+1];
                    wSb = sm.wsf[lane*4+2]; wP  = sm.wsf[lane*4+3];
                    wc  = sm.wsum[lane];
                }
#pragma unroll
                for (int d = 1; d < 8; d <<= 1) {
                    const float uSr = __shfl_up_sync(FULL, wSr, d);
                    const float uSg = __shfl_up_sync(FULL, wSg, d);
                    const float uSb = __shfl_up_sync(FULL, wSb, d);
                    const float uP  = __shfl_up_sync(FULL, wP,  d);
                    const int   uc  = __shfl_up_sync(FULL, wc,  d);
                    if (lane >= d) {
                        wSr = fmaf(uP, wSr, uSr);
                        wSg = fmaf(uP, wSg, uSg);
                        wSb = fmaf(uP, wSb, uSb);
                        wP *= uP;
                        wc += uc;
                    }
                }
                float xSr = __shfl_up_sync(FULL, wSr, 1);
                float xSg = __shfl_up_sync(FULL, wSg, 1);
                float xSb = __shfl_up_sync(FULL, wSb, 1);
                float xP  = __shfl_up_sync(FULL, wP,  1);
                int   xc  = __shfl_up_sync(FULL, wc,  1);
                if (lane == 0) { xSr = 0.f; xSg = 0.f; xSb = 0.f; xP = 1.f; xc = 0; }
                if (lane < 8) {
                    sm.wsf2[lane*4+0] = xSr; sm.wsf2[lane*4+1] = xSg;
                    sm.wsf2[lane*4+2] = xSb; sm.wsf2[lane*4+3] = xP;
                    sm.wsum2[lane] = xc;
                }
                if (lane == 7) {
                    sm.wsf2[32] = wSr; sm.wsf2[33] = wSg;
                    sm.wsf2[34] = wSb; sm.wsf2[35] = wP;
                    sm.sncnt = wc;
                }
            }
            __syncthreads();

            const float oSr = sm.wsf2[wd*4+0], oSg = sm.wsf2[wd*4+1];
            const float oSb = sm.wsf2[wd*4+2], oP  = sm.wsf2[wd*4+3];
            const int ioff = sm.wsum2[wd];
            const int ncnt = sm.sncnt;

            float eSr = __shfl_up_sync(FULL, vSr, 1);
            float eSg = __shfl_up_sync(FULL, vSg, 1);
            float eSb = __shfl_up_sync(FULL, vSb, 1);
            float eP  = __shfl_up_sync(FULL, vP,  1);
            if (lane == 0) { eSr = 0.f; eSg = 0.f; eSb = 0.f; eP = 1.f; }
            const float ESr = fmaf(oP, eSr, oSr);
            const float ESg = fmaf(oP, eSg, oSg);
            const float ESb = fmaf(oP, eSb, oSb);
            const float EP  = oP * eP;

            const int nidx = ioff + __popc(nbits & ((1u << lane) - 1u));
            if (isnear) {
                sm.sSr[nidx] = ESr; sm.sSg[nidx] = ESg; sm.sSb[nidx] = ESb; sm.sP[nidx] = EP;
                sm.n0[nidx] = la;
            }
            __syncthreads();

            if (isnear) {
                float pSr = 0.f, pSg = 0.f, pSb = 0.f, pP = 1.f;
                if (nidx > 0) {
                    pSr = sm.sSr[nidx-1]; pSg = sm.sSg[nidx-1];
                    pSb = sm.sSb[nidx-1]; pP = sm.sP[nidx-1];
                }
                const float ir = rcpf(pP);
                const float gSr = (ESr - pSr) * ir;
                const float gSg = (ESg - pSg) * ir;
                const float gSb = (ESb - pSb) * ir;
                const float gP  = EP * ir;
                const float gcr = gP * lb.w, gcg = gP * lc.x, gcb = gP * lc.y;
                sm.n1[nidx] = make_float2(lb.y, -gP);
                sm.p0[nidx] = make_ulonglong2(pk2(lb.x, lb.x), pk2(gcr, gcr));
                sm.p1[nidx] = make_ulonglong2(pk2(gcg, gcg), pk2(gcb, gcb));
                sm.p2[nidx] = make_ulonglong2(pk2(gSr, gSr), pk2(gSg, gSg));
                sm.p3[nidx] = make_ulonglong2(pk2(gSb, gSb), pk2(gP, gP));
            }
            if (tid == 0) {
                const float tSr = sm.wsf2[32], tSg = sm.wsf2[33];
                const float tSb = sm.wsf2[34], tP  = sm.wsf2[35];
                if (ncnt > 0) {
                    const float lSr = sm.sSr[ncnt-1], lSg = sm.sSg[ncnt-1];
                    const float lSb = sm.sSb[ncnt-1], lP = sm.sP[ncnt-1];
                    const float ir = rcpf(lP);
                    sm.tailSr = (tSr - lSr) * ir;
                    sm.tailSg = (tSg - lSg) * ir;
                    sm.tailSb = (tSb - lSb) * ir;
                    sm.tailP  = tP * ir;
                } else {
                    sm.tailSr = tSr; sm.tailSg = tSg; sm.tailSb = tSb; sm.tailP = tP;
                }
            }
            __syncthreads();

            if (!dead) {
#pragma unroll 2
                for (int t = 0; t < ncnt; t++) {
                    const float4     f0 = sm.n0[t];
                    const float2     h  = sm.n1[t];
                    const ulonglong2 q0 = sm.p0[t];
                    const ulonglong2 q1 = sm.p1[t];
                    const ulonglong2 q2 = sm.p2[t];
                    const ulonglong2 q3 = sm.p3[t];
                    const float dx  = X - f0.x;
                    const float tq  = fmaf(f0.z, dx * dx, h.x);
                    const float cdx = f0.w * dx;
                    const float dy0 = Yf0 - f0.y, dy1 = Yf1 - f0.y;
                    const u64 dy2   = pk2(dy0, dy1);
                    const u64 inner = fma2(q0.x, dy2, pk2(cdx, cdx));
                    const u64 e2    = fma2(dy2, inner, pk2(tq, tq));
                    float e0, e1; upk2(e0, e1, e2);
                    const float a0 = fminf(fmaxf(ex2f(e0), 0.01f), 0.99f);
                    const float a1 = fminf(fmaxf(ex2f(e1), 0.01f), 0.99f);
                    const u64 a2 = pk2(a0, a1);
                    const u64 sR = fma2(a2, q0.y, q2.x);
                    const u64 sG = fma2(a2, q1.x, q2.y);
                    const u64 sB = fma2(a2, q1.y, q3.x);
                    CR2 = fma2(T2, sR, CR2);
                    CG2 = fma2(T2, sG, CG2);
                    CB2 = fma2(T2, sB, CB2);
                    const u64 u2 = fma2(a2, pk2(h.y, h.y), q3.y);
                    T2 = mul2(T2, u2);
                }
                CR2 = fma2(T2, pk2(sm.tailSr, sm.tailSr), CR2);
                CG2 = fma2(T2, pk2(sm.tailSg, sm.tailSg), CG2);
                CB2 = fma2(T2, pk2(sm.tailSb, sm.tailSb), CB2);
                T2 = mul2(T2, pk2(sm.tailP, sm.tailP));
                float T0f, T1f; upk2(T0f, T1f, T2);
                if (T0f < 1e-7f && T1f < 1e-7f) dead = true;
            }
            if (__syncthreads_count(dead ? 0 : 1) == 0) break;
        }

        if (px_active) {
            float C00, C10, C01, C11, C02, C12;
            upk2(C00, C10, CR2);
            upk2(C01, C11, CG2);
            upk2(C02, C12, CB2);
            const int ob0 = (Xi * IMG_W + Yi0) * 3;
            out[ob0 + 0] = C00; out[ob0 + 1] = C01; out[ob0 + 2] = C02;
            const int ob1 = (Xi * IMG_W + Yi1) * 3;
            out[ob1 + 0] = C10; out[ob1 + 1] = C11; out[ob1 + 2] = C12;
        }
    }
}

extern "C" void kernel_launch(void* const* d_in, const int* in_sizes, int n_in,
                              void* d_out, int out_size)
{
    const float* pos2d   = (const float*)d_in[0];
    const float* cov2d   = (const float*)d_in[1];
    const float* opacity = (const float*)d_in[2];
    const float* color   = (const float*)d_in[3];
    float* out = (float*)d_out;

    fused_kernel<<<NB, BLOCK>>>(pos2d, cov2d, opacity, color, out);
}